// round 17
// baseline (speedup 1.0000x reference)
#include <cuda_runtime.h>
#include <cuda_fp16.h>
#include <cstdint>

#define NN 50000
#define EE 800000
#define RR 8
#define DD 128
#define KC 1152        // 8*128 relation cols + 128 root cols
#define LN_EPS 1e-5f
#define NTILES 391     // ceil(50000/128)
#define YSTRIDE 32     // persistent CTAs per column block

// ---------------- scratch (device globals) ---------------------------------
__device__ __align__(16) __half g_Y[NN * KC];           // projections (+root), fp16
__device__ __align__(16) __half g_Xh[NN * DD];          // layer input (fp16)
__device__ __align__(16) __half g_Wall[3 * KC * DD];    // packed weights, 3 layers
__device__ __align__(16) float g_half[NN * 64];         // agg partial (cols 0..63)
__device__ float g_inv[NN * RR];                        // cnt then 1/max(cnt,1)
__device__ int   g_deg[NN];
__device__ int   g_cur[NN];
__device__ int   g_rowptr[NN + 1];
__device__ int   g_csr[EE];                             // src*8 + type
__device__ int   g_part[256];

// ---------------- helpers ---------------------------------------------------
__device__ __forceinline__ uint32_t smem_u32(const void* p) {
    uint32_t a;
    asm("{ .reg .u64 t; cvta.to.shared.u64 t, %1; cvt.u32.u64 %0, t; }"
        : "=r"(a) : "l"(p));
    return a;
}

#define LDSM4(r0, r1, r2, r3, addr) asm volatile( \
    "ldmatrix.sync.aligned.m8n8.x4.shared.b16 {%0,%1,%2,%3}, [%4];" \
    : "=r"(r0), "=r"(r1), "=r"(r2), "=r"(r3) : "r"(addr))

#define MMA_F16(c, a, b0, b1) asm volatile( \
    "mma.sync.aligned.m16n8k16.row.col.f32.f16.f16.f32 " \
    "{%0,%1,%2,%3}, {%4,%5,%6,%7}, {%8,%9}, {%0,%1,%2,%3};" \
    : "+f"((c)[0]), "+f"((c)[1]), "+f"((c)[2]), "+f"((c)[3]) \
    : "r"((a)[0]), "r"((a)[1]), "r"((a)[2]), "r"((a)[3]), "r"(b0), "r"(b1))

// cp.async 16B with dynamic src-size (0 => zero-fill)
#define CP_ASYNC16(dst, src, ssz) asm volatile( \
    "cp.async.cg.shared.global [%0], [%1], 16, %2;" \
    :: "r"(dst), "l"(src), "r"(ssz) : "memory")
#define CP_COMMIT() asm volatile("cp.async.commit_group;" ::: "memory")
#define CP_WAIT(n)  asm volatile("cp.async.wait_group %0;" :: "n"(n) : "memory")

// ---------------- edge-structure kernels ------------------------------------
__global__ void zero_all_kernel() {
    int i = blockIdx.x * blockDim.x + threadIdx.x;
    if (i < NN * RR) g_inv[i] = 0.0f;
    if (i < NN) g_cur[i] = 0;
}

__global__ void count_kernel(const int* __restrict__ ei, const int* __restrict__ et) {
    int e = blockIdx.x * blockDim.x + threadIdx.x;
    if (e < EE) {
        int dst = ei[EE + e];
        atomicAdd(&g_inv[dst * RR + et[e]], 1.0f);
    }
}

__global__ void deg_inv_kernel() {
    int n = blockIdx.x * blockDim.x + threadIdx.x;
    if (n >= NN) return;
    float4 a = *(const float4*)(g_inv + n * RR);
    float4 b = *(const float4*)(g_inv + n * RR + 4);
    g_deg[n] = (int)(a.x + a.y + a.z + a.w + b.x + b.y + b.z + b.w);
    a.x = 1.0f / fmaxf(a.x, 1.0f); a.y = 1.0f / fmaxf(a.y, 1.0f);
    a.z = 1.0f / fmaxf(a.z, 1.0f); a.w = 1.0f / fmaxf(a.w, 1.0f);
    b.x = 1.0f / fmaxf(b.x, 1.0f); b.y = 1.0f / fmaxf(b.y, 1.0f);
    b.z = 1.0f / fmaxf(b.z, 1.0f); b.w = 1.0f / fmaxf(b.w, 1.0f);
    *(float4*)(g_inv + n * RR) = a;
    *(float4*)(g_inv + n * RR + 4) = b;
}

__global__ void deg_partial_kernel() {
    __shared__ int s[256];
    int i = blockIdx.x * 256 + threadIdx.x;
    int v = (i < NN) ? g_deg[i] : 0;
    s[threadIdx.x] = v;
    __syncthreads();
    for (int off = 128; off > 0; off >>= 1) {
        if (threadIdx.x < off) s[threadIdx.x] += s[threadIdx.x + off];
        __syncthreads();
    }
    if (threadIdx.x == 0) g_part[blockIdx.x] = s[0];
}

__global__ void scan_part_kernel(int nblocks) {
    __shared__ int s[512];
    int t = threadIdx.x;
    int v = (t < nblocks) ? g_part[t] : 0;
    s[t] = v;
    __syncthreads();
    int acc = v;
    for (int off = 1; off < 256; off <<= 1) {
        int add = (t >= off) ? s[t - off] : 0;
        __syncthreads();
        s[t] = acc = acc + add;
        __syncthreads();
    }
    if (t < nblocks) g_part[t] = s[t] - v;
}

__global__ void rowptr_kernel() {
    __shared__ int s[512];
    int t = threadIdx.x;
    int i = blockIdx.x * 256 + t;
    int v = (i < NN) ? g_deg[i] : 0;
    s[t] = v;
    __syncthreads();
    int acc = v;
    for (int off = 1; off < 256; off <<= 1) {
        int add = (t >= off) ? s[t - off] : 0;
        __syncthreads();
        s[t] = acc = acc + add;
        __syncthreads();
    }
    if (i < NN) g_rowptr[i] = g_part[blockIdx.x] + s[t] - v;
    if (i == NN) g_rowptr[NN] = EE;
}

__global__ void fill_kernel(const int* __restrict__ ei, const int* __restrict__ et) {
    int e = blockIdx.x * blockDim.x + threadIdx.x;
    if (e < EE) {
        int dst = ei[EE + e];
        int p = atomicAdd(&g_cur[dst], 1);
        g_csr[g_rowptr[dst] + p] = (ei[e] << 3) | et[e];
    }
}

// ---------------- gather + convert ------------------------------------------
__global__ void gather_kernel(const int* __restrict__ node_ids,
                              const float* __restrict__ emb) {
    int idx = blockIdx.x * blockDim.x + threadIdx.x;
    if (idx >= NN * 32) return;
    int n = idx >> 5;
    int c4 = idx & 31;
    int src = node_ids[n];
    float4 v = ((const float4*)emb)[src * 32 + c4];
    __half2 h0 = __floats2half2_rn(v.x, v.y);
    __half2 h1 = __floats2half2_rn(v.z, v.w);
    uint32_t* xh = (uint32_t*)g_Xh;
    xh[n * 64 + c4 * 2]     = *reinterpret_cast<uint32_t*>(&h0);
    xh[n * 64 + c4 * 2 + 1] = *reinterpret_cast<uint32_t*>(&h1);
}

// pack W[r][d][o], root[d][o] -> Wall[slot][c][d] fp16
__global__ void pack_kernel(const float* __restrict__ W, const float* __restrict__ root,
                            int slot) {
    int idx = blockIdx.x * blockDim.x + threadIdx.x;
    if (idx >= KC * DD) return;
    int c = idx >> 7;
    int d = idx & 127;
    float v;
    if (c < RR * DD) v = W[((c >> 7) * DD + d) * DD + (c & 127)];
    else             v = root[d * DD + (c - RR * DD)];
    g_Wall[(size_t)slot * KC * DD + idx] = __float2half_rn(v);
}

// ---------------- HMMA GEMM: Y[N,1152] = X[N,128] @ W^T ---------------------
// Persistent CTAs: grid (9, 32) = 288 CTAs, 2/SM (102 KB smem).
// B tile loaded once; A double-buffer cp.async prefetch; staged epilogue.
#define LDS_ROW 272          // 136 halves per smem row (pad 128+8)
#define SM_B   0
#define SM_A0  34816
#define SM_A1  69632
#define GEMM_SMEM 104448

__device__ __forceinline__ void load_A_tile(uint32_t sb, uint32_t abase,
                                            int tile, int tid) {
#pragma unroll
    for (int i = 0; i < 8; i++) {
        int idx = tid + i * 256;
        int row = idx >> 4;
        int ch = idx & 15;
        int gn = tile * 128 + row;
        uint32_t ssz = (gn < NN) ? 16u : 0u;
        const char* src = (const char*)(g_Xh + (size_t)gn * DD) + ch * 16;
        CP_ASYNC16(sb + abase + row * LDS_ROW + ch * 16, src, ssz);
    }
}

__global__ __launch_bounds__(256, 2) void gemm_kernel(int slot) {
    extern __shared__ char smem[];
    const uint32_t sb = smem_u32(smem);
    const int tid = threadIdx.x, wid = tid >> 5, lane = tid & 31;
    const int cb = blockIdx.x * 128;
    const int it0 = blockIdx.y;
    const __half* Wbase = g_Wall + (size_t)slot * KC * DD;

    // B tile (once) + first two A tiles
#pragma unroll
    for (int i = 0; i < 8; i++) {
        int idx = tid + i * 256;
        int row = idx >> 4;
        int ch = idx & 15;
        const char* src = (const char*)(Wbase + (size_t)(cb + row) * DD) + ch * 16;
        CP_ASYNC16(sb + SM_B + row * LDS_ROW + ch * 16, src, 16u);
    }
    load_A_tile(sb, SM_A0, it0, tid);
    CP_COMMIT();
    load_A_tile(sb, SM_A1, it0 + YSTRIDE, tid);
    CP_COMMIT();

    // warp layout: 4 along M (32 rows), 2 along N (64 cols)
    const int wm = (wid >> 1) * 32;
    const int wn = (wid & 1) * 64;
    const uint32_t aRow = wm + (lane & 15);
    const uint32_t aOff = (lane >> 4) * 16;
    const uint32_t aRel = aRow * LDS_ROW + aOff;
    const uint32_t bRow = wn + ((lane >> 4) & 1) * 8 + (lane & 7);
    const uint32_t bOff = ((lane >> 3) & 1) * 16;
    const uint32_t bHi = sb + SM_B + bRow * LDS_ROW + bOff;

    CP_WAIT(1);               // B + A(it0) ready
    __syncthreads();

    int buf = 0;
    for (int it = it0; it < NTILES; it += YSTRIDE) {
        const uint32_t abase = buf ? SM_A1 : SM_A0;
        const uint32_t aAd = sb + abase + aRel;

        float acc[2][8][4];
#pragma unroll
        for (int mt = 0; mt < 2; mt++)
#pragma unroll
            for (int nt = 0; nt < 8; nt++)
#pragma unroll
                for (int k = 0; k < 4; k++) acc[mt][nt][k] = 0.f;

#pragma unroll
        for (int ks = 0; ks < 8; ks++) {
            uint32_t ah[2][4];
#pragma unroll
            for (int mt = 0; mt < 2; mt++) {
                uint32_t o = mt * (16 * LDS_ROW) + ks * 32;
                LDSM4(ah[mt][0], ah[mt][1], ah[mt][2], ah[mt][3], aAd + o);
            }
#pragma unroll
            for (int bt = 0; bt < 4; bt++) {
                uint32_t bh[4];
                uint32_t o = bt * (16 * LDS_ROW) + ks * 32;
                LDSM4(bh[0], bh[1], bh[2], bh[3], bHi + o);
#pragma unroll
                for (int mt = 0; mt < 2; mt++) {
#pragma unroll
                    for (int ni = 0; ni < 2; ni++) {
                        int nt = bt * 2 + ni;
                        int bi = ni * 2;
                        MMA_F16(acc[mt][nt], ah[mt], bh[bi], bh[bi + 1]);
                    }
                }
            }
        }

        // stage fp16 tile into the just-consumed A buffer, then coalesced STG
        __syncthreads();
        {
            const int rBase = wm + (lane >> 2);
            const int cBase = wn + (lane & 3) * 2;
#pragma unroll
            for (int mt = 0; mt < 2; mt++) {
#pragma unroll
                for (int nt = 0; nt < 8; nt++) {
                    uint32_t a0 = sb + abase + (rBase + mt * 16) * LDS_ROW
                                + (cBase + nt * 8) * 2;
                    __half2 h0 = __floats2half2_rn(acc[mt][nt][0], acc[mt][nt][1]);
                    __half2 h1 = __floats2half2_rn(acc[mt][nt][2], acc[mt][nt][3]);
                    asm volatile("st.shared.b32 [%0], %1;"
                                 :: "r"(a0), "r"(*(uint32_t*)&h0) : "memory");
                    asm volatile("st.shared.b32 [%0], %1;"
                                 :: "r"(a0 + 8 * LDS_ROW), "r"(*(uint32_t*)&h1) : "memory");
                }
            }
        }
        __syncthreads();
#pragma unroll
        for (int i = 0; i < 8; i++) {
            int idx = tid + i * 256;
            int row = idx >> 4;
            int ch = idx & 15;
            int gn = it * 128 + row;
            if (gn < NN) {
                uint4 v;
                asm volatile("ld.shared.v4.b32 {%0,%1,%2,%3}, [%4];"
                             : "=r"(v.x), "=r"(v.y), "=r"(v.z), "=r"(v.w)
                             : "r"(sb + abase + row * LDS_ROW + ch * 16));
                *(uint4*)((char*)(g_Y + (size_t)gn * KC + cb) + ch * 16) = v;
            }
        }
        __syncthreads();   // staging reads done before cp.async overwrites buffer

        int n2 = it + 2 * YSTRIDE;
        if (n2 < NTILES) {
            load_A_tile(sb, abase, n2, tid);
            CP_COMMIT();
        }
        if (it + YSTRIDE < NTILES) {
            if (n2 < NTILES) { CP_WAIT(1); } else { CP_WAIT(0); }
            __syncthreads();   // A(next) visible to all warps
        }
        buf ^= 1;
    }
}

// ---------------- agg phase A: cols [0,64) -> g_half (fp32) -----------------
// Each lane owns 2 consecutive cols (4B fp16 per edge read = 1 L2 line/warp).
__global__ __launch_bounds__(256)
void agg_lo_kernel(const float* __restrict__ bias) {
    int gt = blockIdx.x * blockDim.x + threadIdx.x;
    int row = gt >> 5;
    if (row >= NN) return;
    int lane = gt & 31;

    // root cols [0,64) + bias
    float a0, a1;
    {
        uint32_t p = *(const uint32_t*)(g_Y + (size_t)row * KC + RR * DD + lane * 2);
        float2 f = __half22float2(*reinterpret_cast<__half2*>(&p));
        a0 = f.x + bias[lane * 2];
        a1 = f.y + bias[lane * 2 + 1];
    }

    int beg = g_rowptr[row], end = g_rowptr[row + 1];
    int i = beg;
    for (; i + 2 <= end; i += 2) {
        int pk0 = __ldg(&g_csr[i]);
        int pk1 = __ldg(&g_csr[i + 1]);
        int s0 = pk0 >> 3, t0 = pk0 & 7;
        int s1 = pk1 >> 3, t1 = pk1 & 7;
        float iv0 = __ldg(&g_inv[(row << 3) + t0]);
        float iv1 = __ldg(&g_inv[(row << 3) + t1]);
        uint32_t p0 = __ldg((const uint32_t*)(g_Y + (size_t)s0 * KC + (t0 << 7) + lane * 2));
        uint32_t p1 = __ldg((const uint32_t*)(g_Y + (size_t)s1 * KC + (t1 << 7) + lane * 2));
        float2 e0 = __half22float2(*reinterpret_cast<__half2*>(&p0));
        a0 = fmaf(iv0, e0.x, a0);
        a1 = fmaf(iv0, e0.y, a1);
        float2 e1 = __half22float2(*reinterpret_cast<__half2*>(&p1));
        a0 = fmaf(iv1, e1.x, a0);
        a1 = fmaf(iv1, e1.y, a1);
    }
    for (; i < end; i++) {
        int pk = __ldg(&g_csr[i]);
        int src = pk >> 3, t = pk & 7;
        float iv = __ldg(&g_inv[(row << 3) + t]);
        uint32_t p = __ldg((const uint32_t*)(g_Y + (size_t)src * KC + (t << 7) + lane * 2));
        float2 f = __half22float2(*reinterpret_cast<__half2*>(&p));
        a0 = fmaf(iv, f.x, a0);
        a1 = fmaf(iv, f.y, a1);
    }

    *(float2*)(g_half + (size_t)row * 64 + lane * 2) = make_float2(a0, a1);
}

// ---------------- agg phase B: cols [64,128) + LN + finalize ----------------
__global__ __launch_bounds__(256)
void agg_hi_kernel(const float* __restrict__ bias, const float* __restrict__ gma,
                   const float* __restrict__ bta, float* __restrict__ ext_out,
                   int do_ln) {
    int gt = blockIdx.x * blockDim.x + threadIdx.x;
    int row = gt >> 5;
    if (row >= NN) return;
    int lane = gt & 31;

    // root cols [64,128) + bias
    float a2, a3;
    {
        uint32_t p = *(const uint32_t*)(g_Y + (size_t)row * KC + RR * DD + 64 + lane * 2);
        float2 f = __half22float2(*reinterpret_cast<__half2*>(&p));
        a2 = f.x + bias[64 + lane * 2];
        a3 = f.y + bias[64 + lane * 2 + 1];
    }

    int beg = g_rowptr[row], end = g_rowptr[row + 1];
    int i = beg;
    for (; i + 2 <= end; i += 2) {
        int pk0 = __ldg(&g_csr[i]);
        int pk1 = __ldg(&g_csr[i + 1]);
        int s0 = pk0 >> 3, t0 = pk0 & 7;
        int s1 = pk1 >> 3, t1 = pk1 & 7;
        float iv0 = __ldg(&g_inv[(row << 3) + t0]);
        float iv1 = __ldg(&g_inv[(row << 3) + t1]);
        uint32_t p0 = __ldg((const uint32_t*)(g_Y + (size_t)s0 * KC + (t0 << 7) + 64 + lane * 2));
        uint32_t p1 = __ldg((const uint32_t*)(g_Y + (size_t)s1 * KC + (t1 << 7) + 64 + lane * 2));
        float2 e0 = __half22float2(*reinterpret_cast<__half2*>(&p0));
        a2 = fmaf(iv0, e0.x, a2);
        a3 = fmaf(iv0, e0.y, a3);
        float2 e1 = __half22float2(*reinterpret_cast<__half2*>(&p1));
        a2 = fmaf(iv1, e1.x, a2);
        a3 = fmaf(iv1, e1.y, a3);
    }
    for (; i < end; i++) {
        int pk = __ldg(&g_csr[i]);
        int src = pk >> 3, t = pk & 7;
        float iv = __ldg(&g_inv[(row << 3) + t]);
        uint32_t p = __ldg((const uint32_t*)(g_Y + (size_t)src * KC + (t << 7) + 64 + lane * 2));
        float2 f = __half22float2(*reinterpret_cast<__half2*>(&p));
        a2 = fmaf(iv, f.x, a2);
        a3 = fmaf(iv, f.y, a3);
    }

    // lo partial (cols 2l, 2l+1)
    float2 lo = *(const float2*)(g_half + (size_t)row * 64 + lane * 2);
    float a0 = lo.x, a1 = lo.y;

    if (do_ln) {
        float s = a0 + a1 + a2 + a3;
#pragma unroll
        for (int off = 16; off > 0; off >>= 1) s += __shfl_xor_sync(0xffffffffu, s, off);
        float mu = s * (1.0f / 128.0f);
        float d0 = a0 - mu, d1 = a1 - mu, d2 = a2 - mu, d3 = a3 - mu;
        float q = d0 * d0 + d1 * d1 + d2 * d2 + d3 * d3;
#pragma unroll
        for (int off = 16; off > 0; off >>= 1) q += __shfl_xor_sync(0xffffffffu, q, off);
        float rs = rsqrtf(q * (1.0f / 128.0f) + LN_EPS);
        float g0 = gma[lane * 2],      g1 = gma[lane * 2 + 1];
        float g2 = gma[64 + lane * 2], g3 = gma[64 + lane * 2 + 1];
        float t0 = bta[lane * 2],      t1 = bta[lane * 2 + 1];
        float t2 = bta[64 + lane * 2], t3 = bta[64 + lane * 2 + 1];
        float o0 = fmaxf(d0 * rs * g0 + t0, 0.f);
        float o1 = fmaxf(d1 * rs * g1 + t1, 0.f);
        float o2 = fmaxf(d2 * rs * g2 + t2, 0.f);
        float o3 = fmaxf(d3 * rs * g3 + t3, 0.f);
        __half2 h0 = __floats2half2_rn(o0, o1);
        __half2 h1 = __floats2half2_rn(o2, o3);
        uint32_t* xh = (uint32_t*)g_Xh;
        xh[row * 64 + lane]      = *reinterpret_cast<uint32_t*>(&h0);
        xh[row * 64 + 32 + lane] = *reinterpret_cast<uint32_t*>(&h1);
    } else {
        *(float2*)(ext_out + (size_t)row * DD + lane * 2)      = make_float2(a0, a1);
        *(float2*)(ext_out + (size_t)row * DD + 64 + lane * 2) = make_float2(a2, a3);
    }
}

// ---------------- launch ----------------------------------------------------
extern "C" void kernel_launch(void* const* d_in, const int* in_sizes, int n_in,
                              void* d_out, int out_size) {
    const int*   node_ids = (const int*)d_in[0];
    const int*   ei       = (const int*)d_in[1];
    const int*   et       = (const int*)d_in[2];
    const float* emb      = (const float*)d_in[3];
    const float* W1 = (const float*)d_in[4],  *root1 = (const float*)d_in[5];
    const float* b1 = (const float*)d_in[6],  *g1 = (const float*)d_in[7];
    const float* be1 = (const float*)d_in[8];
    const float* W2 = (const float*)d_in[9],  *root2 = (const float*)d_in[10];
    const float* b2 = (const float*)d_in[11], *g2 = (const float*)d_in[12];
    const float* be2 = (const float*)d_in[13];
    const float* W3 = (const float*)d_in[14], *root3 = (const float*)d_in[15];
    const float* b3 = (const float*)d_in[16];
    float* out = (float*)d_out;

    static cudaStream_t s2 = nullptr;
    static cudaEvent_t evFork = nullptr, evJoin = nullptr, evPack = nullptr;
    static int init_done = 0;
    if (!init_done) {
        cudaFuncSetAttribute(gemm_kernel, cudaFuncAttributeMaxDynamicSharedMemorySize,
                             GEMM_SMEM);
        cudaStreamCreateWithFlags(&s2, cudaStreamNonBlocking);
        cudaEventCreateWithFlags(&evFork, cudaEventDisableTiming);
        cudaEventCreateWithFlags(&evJoin, cudaEventDisableTiming);
        cudaEventCreateWithFlags(&evPack, cudaEventDisableTiming);
        init_done = 1;
    }

    const int T = 256;
    const int NB_NODE = (NN + T - 1) / T;          // 196
    dim3 gemm_grid(KC / 128, YSTRIDE);             // 9 x 32 persistent CTAs

    // Fork: packs + edge-structure chain on s2, concurrent with gather/gemm1.
    cudaEventRecord(evFork, 0);
    cudaStreamWaitEvent(s2, evFork, 0);

    pack_kernel<<<(KC * DD + T - 1) / T, T, 0, s2>>>(W1, root1, 0);
    cudaEventRecord(evPack, s2);                    // gemm1 needs only pack1
    pack_kernel<<<(KC * DD + T - 1) / T, T, 0, s2>>>(W2, root2, 1);
    pack_kernel<<<(KC * DD + T - 1) / T, T, 0, s2>>>(W3, root3, 2);
    zero_all_kernel<<<(NN * RR + T - 1) / T, T, 0, s2>>>();
    count_kernel<<<(EE + T - 1) / T, T, 0, s2>>>(ei, et);
    deg_inv_kernel<<<NB_NODE, T, 0, s2>>>();
    deg_partial_kernel<<<NB_NODE, T, 0, s2>>>();
    scan_part_kernel<<<1, T, 0, s2>>>(NB_NODE);
    rowptr_kernel<<<NB_NODE, T, 0, s2>>>();
    fill_kernel<<<(EE + T - 1) / T, T, 0, s2>>>(ei, et);
    cudaEventRecord(evJoin, s2);

    // Main stream: gather, then layer-1 GEMM (after pack1)
    gather_kernel<<<(NN * 32 + T - 1) / T, T>>>(node_ids, emb);
    cudaStreamWaitEvent(0, evPack, 0);
    gemm_kernel<<<gemm_grid, T, GEMM_SMEM>>>(0);

    // Join: agg needs CSR + counts
    cudaStreamWaitEvent(0, evJoin, 0);

    // layer 1 agg (two half-column passes) + layer 2/3
    agg_lo_kernel<<<(NN * 32 + T - 1) / T, T>>>(b1);
    agg_hi_kernel<<<(NN * 32 + T - 1) / T, T>>>(b1, g1, be1, nullptr, 1);
    gemm_kernel<<<gemm_grid, T, GEMM_SMEM>>>(1);
    agg_lo_kernel<<<(NN * 32 + T - 1) / T, T>>>(b2);
    agg_hi_kernel<<<(NN * 32 + T - 1) / T, T>>>(b2, g2, be2, nullptr, 1);
    gemm_kernel<<<gemm_grid, T, GEMM_SMEM>>>(2);
    agg_lo_kernel<<<(NN * 32 + T - 1) / T, T>>>(b3);
    agg_hi_kernel<<<(NN * 32 + T - 1) / T, T>>>(b3, nullptr, nullptr, out, 0);

    (void)in_sizes; (void)n_in; (void)out_size;
}